// round 15
// baseline (speedup 1.0000x reference)
#include <cuda_runtime.h>

// reblurWithKernel: spatially-varying 33x33 blur, per-4x4-block kernels.
// out[c,h,w] = sum_{u,v} in[clamp(h+u-16),clamp(w+v-16)] * K[u*33+v, h/4, w/4]
//
// R13: all-FFMA2 (fma.rn.f32x2) without R9's smem duplication:
//  - smem copy 1: channels 0,1 interleaved per pixel (36 rows x 160 pairs)
//  - smem copy 2: channel 2 row-pair interleaved (35 pair-rows: 18 even+17 odd)
//  - 12 warps = 4 u-quarters x 3 roles: A = (c0,c1) rows oi{0,1},
//    B = (c0,c1) rows oi{2,3}, C = c2 row-pairs (oi0,oi1),(oi2,oi3).
//    Every role does 264 FFMA2 per u -> perfectly balanced.
//  - pair-rows stored split into A-chunks (pair idx 0,1 mod 4) / B-chunks
//    (2,3 mod 4) so each warp lds2 (16B/lane) is lane-dense.
//  - kr software pipelining (krA taps0..15 prefetched / krB taps16..32) and
//    front-loaded u=32 slice kept from R12. 91KB smem -> 2 CTAs/SM.

#define KW     33
#define BLK    4
#define PAD    16
#define HH     512
#define WW     512
#define HB     128
#define WBNUM  128
#define HW     (HH*WW)
#define KSTR   (HB*WBNUM)          // 16384 elements between taps
#define TWB    32
#define ROWDU  164                 // ull per pair-row (82 A + 82 B)
#define ROWDB  1312                // bytes per pair-row
#define BOFF   656u                // byte offset of B chunk region
#define NROWS01 36
#define NPAIR2  35                 // 18 even-start + 17 odd-start pair rows
#define OFF2B  (NROWS01*ROWDB)     // 47232 byte offset of c2 region
#define NTH    384
#define SMEM_BYTES ((NROWS01 + NPAIR2) * ROWDB)   // 93152
#define NPUNITS ((NROWS01 + NPAIR2) * 160)        // 11360 pair stores

typedef unsigned long long ull;

__device__ __forceinline__ ull pack2(float lo, float hi) {
    ull r;
    asm("mov.b64 %0, {%1, %2};"
        : "=l"(r) : "r"(__float_as_uint(lo)), "r"(__float_as_uint(hi)));
    return r;
}
__device__ __forceinline__ void unpack2(ull v, float& lo, float& hi) {
    unsigned int a, b;
    asm("mov.b64 {%0, %1}, %2;" : "=r"(a), "=r"(b) : "l"(v));
    lo = __uint_as_float(a); hi = __uint_as_float(b);
}
__device__ __forceinline__ ull fma2(ull a, ull b, ull c) {
    ull d;
    asm("fma.rn.f32x2 %0, %1, %2, %3;" : "=l"(d) : "l"(a), "l"(b), "l"(c));
    return d;
}
__device__ __forceinline__ ull add2(ull a, ull b) {
    ull d;
    asm("add.rn.f32x2 %0, %1, %2;" : "=l"(d) : "l"(a), "l"(b));
    return d;
}
__device__ __forceinline__ void lds2(unsigned int addr, ull& a, ull& b) {
    asm volatile("ld.shared.v2.u64 {%0, %1}, [%2];"
                 : "=l"(a), "=l"(b) : "r"(addr));
}

// 4 consecutive taps. Window pairs rel t=0..6: a0,a1,b0,b1,a2,a3,b2.
__device__ __forceinline__ void quad_taps(const float* kq,
    ull a0, ull a1, ull b0, ull b1, ull a2, ull a3, ull b2, ull* acc)
{
    ull KK;
    KK = pack2(kq[0], kq[0]);
    acc[0]=fma2(KK,a0,acc[0]); acc[1]=fma2(KK,a1,acc[1]);
    acc[2]=fma2(KK,b0,acc[2]); acc[3]=fma2(KK,b1,acc[3]);
    KK = pack2(kq[1], kq[1]);
    acc[0]=fma2(KK,a1,acc[0]); acc[1]=fma2(KK,b0,acc[1]);
    acc[2]=fma2(KK,b1,acc[2]); acc[3]=fma2(KK,a2,acc[3]);
    KK = pack2(kq[2], kq[2]);
    acc[0]=fma2(KK,b0,acc[0]); acc[1]=fma2(KK,b1,acc[1]);
    acc[2]=fma2(KK,a2,acc[2]); acc[3]=fma2(KK,a3,acc[3]);
    KK = pack2(kq[3], kq[3]);
    acc[0]=fma2(KK,b1,acc[0]); acc[1]=fma2(KK,a2,acc[1]);
    acc[2]=fma2(KK,a3,acc[2]); acc[3]=fma2(KK,b2,acc[3]);
}

// 16 taps (rel 0..15) on one pair-row; first window quad = q0.
__device__ __forceinline__ void conv16(unsigned int rowb, int q0,
                                       const float* kr, ull* acc)
{
    const unsigned int aAddr = rowb + (unsigned)q0 * 16u;
    const unsigned int bAddr = aAddr + BOFF;
    ull a0,a1,b0,b1,a2,a3,b2,b3;
    lds2(aAddr,      a0, a1);
    lds2(bAddr,      b0, b1);
    lds2(aAddr + 16, a2, a3);
    lds2(bAddr + 16, b2, b3);
#pragma unroll
    for (int s = 0; s < 4; s++) {
        quad_taps(kr + 4 * s, a0, a1, b0, b1, a2, a3, b2, acc);
        a0 = a2; a1 = a3; b0 = b2; b1 = b3;
        if (s < 3) {
            lds2(aAddr + (unsigned)(s + 2) * 16u, a2, a3);
            lds2(bAddr + (unsigned)(s + 2) * 16u, b2, b3);
        }
    }
    // final window a0,a1,b0,b1 = rel pairs 16..19 (unused here)
}

// 17 taps (rel 0..16): 16-tap core + extra tap kx on rel pairs 16..19.
__device__ __forceinline__ void conv16t(unsigned int rowb, int q0,
                                        const float* kr, float kx, ull* acc)
{
    const unsigned int aAddr = rowb + (unsigned)q0 * 16u;
    const unsigned int bAddr = aAddr + BOFF;
    ull a0,a1,b0,b1,a2,a3,b2,b3;
    lds2(aAddr,      a0, a1);
    lds2(bAddr,      b0, b1);
    lds2(aAddr + 16, a2, a3);
    lds2(bAddr + 16, b2, b3);
#pragma unroll
    for (int s = 0; s < 4; s++) {
        quad_taps(kr + 4 * s, a0, a1, b0, b1, a2, a3, b2, acc);
        a0 = a2; a1 = a3; b0 = b2; b1 = b3;
        if (s < 3) {
            lds2(aAddr + (unsigned)(s + 2) * 16u, a2, a3);
            lds2(bAddr + (unsigned)(s + 2) * 16u, b2, b3);
        }
    }
    ull KK = pack2(kx, kx);
    acc[0]=fma2(KK,a0,acc[0]); acc[1]=fma2(KK,a1,acc[1]);
    acc[2]=fma2(KK,b0,acc[2]); acc[3]=fma2(KK,b1,acc[3]);
}

// 8 taps (rel 0..7) + optional tap on rel pairs 8..11 (k32; 0 when unused).
__device__ __forceinline__ void conv8(unsigned int rowb, int q0,
                                      const float* kq, float k32, ull* acc)
{
    const unsigned int aAddr = rowb + (unsigned)q0 * 16u;
    const unsigned int bAddr = aAddr + BOFF;
    ull a0,a1,b0,b1,a2,a3,b2,b3;
    lds2(aAddr,      a0, a1);
    lds2(bAddr,      b0, b1);
    lds2(aAddr + 16, a2, a3);
    lds2(bAddr + 16, b2, b3);
    quad_taps(kq, a0, a1, b0, b1, a2, a3, b2, acc);
    a0 = a2; a1 = a3; b0 = b2; b1 = b3;
    lds2(aAddr + 32, a2, a3);
    lds2(bAddr + 32, b2, b3);
    quad_taps(kq + 4, a0, a1, b0, b1, a2, a3, b2, acc);
    // rel pairs 8..11 = (a2,a3,b2,b3)
    ull KK = pack2(k32, k32);
    acc[0]=fma2(KK,a2,acc[0]); acc[1]=fma2(KK,a3,acc[1]);
    acc[2]=fma2(KK,b2,acc[2]); acc[3]=fma2(KK,b3,acc[3]);
}

__global__ __launch_bounds__(NTH, 2)
void reblur_kernel(const float* __restrict__ img,
                   const float* __restrict__ ker,
                   float* __restrict__ out)
{
    extern __shared__ __align__(16) char smem[];
    unsigned int sbase;
    asm("{ .reg .u64 t; cvta.to.shared.u64 t, %1; cvt.u32.u64 %0, t; }"
        : "=r"(sbase) : "l"(smem));

    const int tid  = threadIdx.x;
    const int WB0  = blockIdx.x * TWB;
    const int HB0  = blockIdx.y;
    const int w    = tid >> 5;
    const int lane = tid & 31;
    const int q    = w & 3;        // u-quarter
    const int role = w >> 2;       // 0=A (c01, oi01), 1=B (c01, oi23), 2=C (c2)
    const int pradd = (q & 1) * 18;

    const float* kbase = ker + HB0 * WBNUM + (WB0 + lane);

    // ---- issue krA (first u-row taps 0..15) + krS (u32 slice) up front ----
    float krA[16], krS[8], k32s;
    {
        const float* kp = kbase + (q * KW) * KSTR;
#pragma unroll
        for (int v = 0; v < 16; v++)
            krA[v] = __ldg(kp + v * KSTR);
        const float* kps = kbase + (32 * KW + 8 * q) * KSTR;
#pragma unroll
        for (int i = 0; i < 8; i++)
            krS[i] = __ldg(kps + i * KSTR);
        k32s = (q == 3) ? __ldg(kbase + (32 * KW + 32) * KSTR) : 0.0f;
    }

    // ---- prologue: build both interleaved smem structures ----
    const int row0 = HB0 * BLK - PAD;
    const int col0 = WB0 * BLK - PAD;
    for (int idx = tid; idx < NPUNITS; idx += NTH) {
        float va, vb;
        int x;
        unsigned int rowoff;
        if (idx < NROWS01 * 160) {                 // (c0,c1) pixel pairs
            int r = idx / 160;
            x = idx - r * 160;
            int ir = min(max(row0 + r, 0), HH - 1);
            int ic = min(max(col0 + x, 0), WW - 1);
            va = img[ir * WW + ic];                // c0
            vb = img[HW + ir * WW + ic];           // c1
            rowoff = (unsigned)(r * ROWDB);
        } else {                                   // c2 row-pairs
            int t  = idx - NROWS01 * 160;
            int pr = t / 160;
            x = t - pr * 160;
            int R0 = (pr < 18) ? (2 * pr) : (2 * (pr - 18) + 1);
            int ir0 = min(max(row0 + R0, 0), HH - 1);
            int ir1 = min(max(row0 + R0 + 1, 0), HH - 1);
            int ic  = min(max(col0 + x, 0), WW - 1);
            va = img[2 * HW + ir0 * WW + ic];
            vb = img[2 * HW + ir1 * WW + ic];
            rowoff = (unsigned)(OFF2B + pr * ROWDB);
        }
        int m = x >> 2, s4 = x & 3;
        int didx = (s4 < 2) ? (2 * m + s4) : (82 + 2 * m + (s4 - 2));
        *reinterpret_cast<ull*>(smem + rowoff + (unsigned)didx * 8u)
            = pack2(va, vb);
    }
    __syncthreads();

    ull accP[4] = {0,0,0,0};   // role A/B: oi(2*role); role C: (oi0,oi1)
    ull accQ[4] = {0,0,0,0};   // role A/B: oi(2*role+1); role C: (oi2,oi3)

    // ---- u=32 slice first (taps 8q..8q+7, + tap32 for q==3) ----
    {
        unsigned int b32 = sbase + ((role == 2)
                         ? (unsigned)(OFF2B + 16 * ROWDB)
                         : (unsigned)((32 + 2 * role) * ROWDB));
        conv8(b32,         lane + 2 * q, krS, k32s, accP);
        conv8(b32 + ROWDB, lane + 2 * q, krS, k32s, accQ);
    }

    // ---- main loop: u = q, q+4, ..., <32 ----
    float krB[17];
#pragma unroll 1
    for (int u = q; u < 32; u += 4) {
        const float* kpu = kbase + (u * KW) * KSTR;
#pragma unroll
        for (int v = 0; v < 17; v++)
            krB[v] = __ldg(kpu + (16 + v) * KSTR);

        const unsigned int b0 = sbase + ((role == 2)
                              ? (unsigned)(OFF2B + (pradd + (u >> 1)) * ROWDB)
                              : (unsigned)((u + 2 * role) * ROWDB));

        conv16(b0,         lane, krA, accP);   // taps 0..15
        conv16(b0 + ROWDB, lane, krA, accQ);

        if (u + 4 < 32) {                      // prefetch next krA
            const float* kp2 = kbase + ((u + 4) * KW) * KSTR;
#pragma unroll
            for (int v = 0; v < 16; v++)
                krA[v] = __ldg(kp2 + v * KSTR);
        }

        conv16t(b0,         lane + 4, krB, krB[16], accP);  // taps 16..32
        conv16t(b0 + ROWDB, lane + 4, krB, krB[16], accQ);
    }

    // ---- combine the 4 u-quarters via smem (reuse patch region) ----
    __syncthreads();
    ull* red = reinterpret_cast<ull*>(smem);
#pragma unroll
    for (int k = 0; k < 4; k++) {
        red[(w * 8 + k) * 32 + lane]     = accP[k];
        red[(w * 8 + 4 + k) * 32 + lane] = accQ[k];
    }
    __syncthreads();

    if (q == 0) {                  // warps 0,4,8 finish their role
#pragma unroll
        for (int p = 1; p < 4; p++) {
            const int ws = w + p;
#pragma unroll
            for (int k = 0; k < 4; k++) {
                accP[k] = add2(accP[k], red[(ws * 8 + k) * 32 + lane]);
                accQ[k] = add2(accQ[k], red[(ws * 8 + 4 + k) * 32 + lane]);
            }
        }
        float lo[4], hi[4], lo2[4], hi2[4];
#pragma unroll
        for (int k = 0; k < 4; k++) {
            unpack2(accP[k], lo[k],  hi[k]);
            unpack2(accQ[k], lo2[k], hi2[k]);
        }
        if (role < 2) {
            const int oi = 2 * role;
            float* o0 = out + (HB0 * BLK + oi) * WW + (WB0 + lane) * BLK;
            *reinterpret_cast<float4*>(o0)      = make_float4(lo[0],lo[1],lo[2],lo[3]);
            *reinterpret_cast<float4*>(o0 + HW) = make_float4(hi[0],hi[1],hi[2],hi[3]);
            float* o1 = o0 + WW;
            *reinterpret_cast<float4*>(o1)      = make_float4(lo2[0],lo2[1],lo2[2],lo2[3]);
            *reinterpret_cast<float4*>(o1 + HW) = make_float4(hi2[0],hi2[1],hi2[2],hi2[3]);
        } else {
            float* o2 = out + 2 * HW + (HB0 * BLK) * WW + (WB0 + lane) * BLK;
            *reinterpret_cast<float4*>(o2 + 0 * WW) = make_float4(lo[0],lo[1],lo[2],lo[3]);
            *reinterpret_cast<float4*>(o2 + 1 * WW) = make_float4(hi[0],hi[1],hi[2],hi[3]);
            *reinterpret_cast<float4*>(o2 + 2 * WW) = make_float4(lo2[0],lo2[1],lo2[2],lo2[3]);
            *reinterpret_cast<float4*>(o2 + 3 * WW) = make_float4(hi2[0],hi2[1],hi2[2],hi2[3]);
        }
    }
}

extern "C" void kernel_launch(void* const* d_in, const int* in_sizes, int n_in,
                              void* d_out, int out_size)
{
    const float* img = (const float*)d_in[0];  // (1,3,512,512) fp32
    const float* ker = (const float*)d_in[1];  // (1,1089,128,128) fp32
    float* out = (float*)d_out;                // (1,3,512,512) fp32
    (void)in_sizes; (void)n_in; (void)out_size;

    cudaFuncSetAttribute(reblur_kernel,
                         cudaFuncAttributeMaxDynamicSharedMemorySize, SMEM_BYTES);

    dim3 grid(WBNUM / TWB, HB);  // (4, 128) = 512 CTAs
    reblur_kernel<<<grid, NTH, SMEM_BYTES>>>(img, ker, out);
}